// round 6
// baseline (speedup 1.0000x reference)
#include <cuda_runtime.h>
#include <cuda_bf16.h>
#include <cstddef>

#define FULL 0xffffffffu

// Folded per-batch weights: K2T[8][512] | T3[8][8][8] | LL3[8][512] | H[8][64]
// = 4096 + 512 + 4096 + 512 = 9216 floats per batch.
__device__ __align__(16) float d_scratch[8 * 9216];

// ---------------------------------------------------------------------------
// Prep: one block per batch. Merge experts with gates, then fold cores.
// Cost is trivial (~100k MACs/batch).
// ---------------------------------------------------------------------------
__global__ void tt_prep(const float* __restrict__ gates,
                        const float* __restrict__ cf,   // [8][1][8][8]
                        const float* __restrict__ cm,   // [6][8][8][8][8]
                        const float* __restrict__ cl)   // [8][8][8][1]
{
    __shared__ float gsh[3200];   // G0[64] | G1..G6[6*512] | G7[64]
    __shared__ float k1[512];     // K1[(m1*8+m0)*8 + p1]
    const int b = blockIdx.x;
    const int tid = threadIdx.x;

    float gt[8];
#pragma unroll
    for (int e = 0; e < 8; e++) gt[e] = gates[b * 8 + e];

    // Merge experts: G_i = sum_e gate[e] * core_i[e]
    for (int idx = tid; idx < 3200; idx += 256) {
        float v = 0.f;
        if (idx < 64) {
#pragma unroll
            for (int e = 0; e < 8; e++) v += gt[e] * cf[e * 64 + idx];
        } else if (idx < 3136) {
            const int i   = (idx - 64) >> 9;
            const int off = (idx - 64) & 511;
#pragma unroll
            for (int e = 0; e < 8; e++) v += gt[e] * cm[i * 4096 + e * 512 + off];
        } else {
            const int off = idx - 3136;
#pragma unroll
            for (int e = 0; e < 8; e++) v += gt[e] * cl[e * 64 + off];
        }
        gsh[idx] = v;
    }
    __syncthreads();

    const float* g0 = gsh;          // [m0][p0]
    const float* g1 = gsh + 64;     // [r][m][p]
    const float* g2 = gsh + 576;
    const float* g3 = gsh + 1088;
    const float* g4 = gsh + 1600;
    const float* g5 = gsh + 2112;
    const float* g6 = gsh + 2624;
    const float* g7 = gsh + 3136;   // [p6][n3]
    float* outp = d_scratch + b * 9216;

    // K1[(m1,m0)][p1] = sum_p0 G0[m0][p0] * G1[p0][m1][p1]
    for (int idx = tid; idx < 512; idx += 256) {
        const int p1 = idx & 7, m0 = (idx >> 3) & 7, m1 = idx >> 6;
        float v = 0.f;
#pragma unroll
        for (int p0 = 0; p0 < 8; p0++) v += g0[m0 * 8 + p0] * g1[p0 * 64 + m1 * 8 + p1];
        k1[idx] = v;
    }

    // T3[p2][m3][p3] = merged mid[2] directly
    for (int idx = tid; idx < 512; idx += 256) outp[4096 + idx] = g3[idx];

    // LL3[q][p5*64 + n0*8 + n1] = sum_p4 G4[q][n0][p4] * G5[p4][n1][p5]
    for (int idx = tid; idx < 4096; idx += 256) {
        const int q = idx >> 9, p5 = (idx >> 6) & 7, n0 = (idx >> 3) & 7, n1 = idx & 7;
        float v = 0.f;
#pragma unroll
        for (int p4 = 0; p4 < 8; p4++) v += g4[q * 64 + n0 * 8 + p4] * g5[p4 * 64 + n1 * 8 + p5];
        outp[4608 + idx] = v;
    }

    // H[r][n2*8+n3] = sum_p6 G6[r][n2][p6] * G7[p6][n3]
    for (int idx = tid; idx < 512; idx += 256) {
        const int r = idx >> 6, n2 = (idx >> 3) & 7, n3 = idx & 7;
        float v = 0.f;
#pragma unroll
        for (int p6 = 0; p6 < 8; p6++) v += g6[r * 64 + n2 * 8 + p6] * g7[p6 * 8 + n3];
        outp[8704 + idx] = v;
    }
    __syncthreads();

    // K2T[p2][m2*64+m1*8+m0] = sum_p1 K1[(m1,m0)][p1] * G2[p1][m2][p2]
    for (int idx = tid; idx < 4096; idx += 256) {
        const int p2 = idx >> 9, c = idx & 511;
        const int m2 = c >> 6, m1 = (c >> 3) & 7, m0 = c & 7;
        float v = 0.f;
#pragma unroll
        for (int p1 = 0; p1 < 8; p1++) v += k1[(m1 * 8 + m0) * 8 + p1] * g2[p1 * 64 + m2 * 8 + p2];
        outp[idx] = v;
    }
}

// ---------------------------------------------------------------------------
// Main: 256 blocks (8 batches x 32), 8 warps/block, 2 tokens/warp.
// ---------------------------------------------------------------------------
__global__ __launch_bounds__(256, 2)
void tt_main(const float* __restrict__ X, float* __restrict__ out)
{
    __shared__ __align__(16) float sw[9216];
    const int b   = blockIdx.x >> 5;
    const int blk = blockIdx.x & 31;
    const int tid = threadIdx.x;

    // Stage weights into smem (36 KB)
    {
        const float4* src = (const float4*)(d_scratch + b * 9216);
        float4* dst = (float4*)sw;
#pragma unroll
        for (int kk = 0; kk < 9; kk++) dst[tid + kk * 256] = src[tid + kk * 256];
    }
    __syncthreads();

    const float* K2T = sw;           // [8][512]
    const float* T3s = sw + 4096;    // [p2][m3][p3]
    const float* LL3 = sw + 4608;    // [8][512]
    const float* Hs  = sw + 8704;    // [8][64]

    const int w  = tid >> 5;
    const int l  = tid & 31;
    const int g  = l >> 2;           // m3 group (0..7)
    const int j  = l & 3;            // sub-lane within m3 group
    const int hi = l >> 4;
    const int lo = l & 15;

    const int tok0 = blk * 16 + w * 2;
    const float* x0 = X + ((size_t)b * 512 + tok0) * 4096;
    const float* x1 = x0 + 4096;
    float* o0 = out + ((size_t)b * 512 + tok0) * 4096;
    float* o1 = o0 + 4096;

    // ---- Stage I: t2[p2][m3] = sum_c X[m3*512+c] * K2T[p2][c] ----
    float a0[8], a1[8];
#pragma unroll
    for (int p = 0; p < 8; p++) { a0[p] = 0.f; a1[p] = 0.f; }
    const int xoff = g * 512 + j * 4;
#pragma unroll 4
    for (int i = 0; i < 32; i++) {
        const float4 v0 = *(const float4*)(x0 + xoff + i * 16);
        const float4 v1 = *(const float4*)(x1 + xoff + i * 16);
        const float* kb = K2T + j * 4 + i * 16;
#pragma unroll
        for (int p = 0; p < 8; p++) {
            const float4 k = *(const float4*)(kb + p * 512);
            a0[p] += v0.x * k.x + v0.y * k.y + v0.z * k.z + v0.w * k.w;
            a1[p] += v1.x * k.x + v1.y * k.y + v1.z * k.z + v1.w * k.w;
        }
    }
    // reduce over j (4 lanes per m3 group)
#pragma unroll
    for (int d = 1; d < 4; d <<= 1) {
#pragma unroll
        for (int p = 0; p < 8; p++) {
            a0[p] += __shfl_xor_sync(FULL, a0[p], d);
            a1[p] += __shfl_xor_sync(FULL, a1[p], d);
        }
    }
    // lane now holds t2[p2][m3=g] for both tokens

    // ---- Stage II: t3[p3] = sum_{p2,m3} t2[p2][m3] * T3[p2][m3][p3] ----
    float t3_0[8], t3_1[8];
#pragma unroll
    for (int p = 0; p < 8; p++) { t3_0[p] = 0.f; t3_1[p] = 0.f; }
#pragma unroll
    for (int p2 = 0; p2 < 8; p2++) {
        const float* tb = T3s + p2 * 64 + g * 8;
        const float4 c0 = *(const float4*)tb;
        const float4 c1 = *(const float4*)(tb + 4);
        t3_0[0] += a0[p2] * c0.x;  t3_0[1] += a0[p2] * c0.y;
        t3_0[2] += a0[p2] * c0.z;  t3_0[3] += a0[p2] * c0.w;
        t3_0[4] += a0[p2] * c1.x;  t3_0[5] += a0[p2] * c1.y;
        t3_0[6] += a0[p2] * c1.z;  t3_0[7] += a0[p2] * c1.w;
        t3_1[0] += a1[p2] * c0.x;  t3_1[1] += a1[p2] * c0.y;
        t3_1[2] += a1[p2] * c0.z;  t3_1[3] += a1[p2] * c0.w;
        t3_1[4] += a1[p2] * c1.x;  t3_1[5] += a1[p2] * c1.y;
        t3_1[6] += a1[p2] * c1.z;  t3_1[7] += a1[p2] * c1.w;
    }
    // butterfly over m3 groups -> every lane holds full t3[0..7]
#pragma unroll
    for (int d = 4; d < 32; d <<= 1) {
#pragma unroll
        for (int p = 0; p < 8; p++) {
            t3_0[p] += __shfl_xor_sync(FULL, t3_0[p], d);
            t3_1[p] += __shfl_xor_sync(FULL, t3_1[p], d);
        }
    }

    // ---- Stage III: t5flat[v] = sum_q t3[q] * LL3[q][v], v = k*32 + l ----
    float t5_0[16], t5_1[16];
#pragma unroll
    for (int k = 0; k < 16; k++) {
        float s0 = 0.f, s1 = 0.f;
#pragma unroll
        for (int q = 0; q < 8; q++) {
            const float wv = LL3[q * 512 + k * 32 + l];
            s0 += t3_0[q] * wv;
            s1 += t3_1[q] * wv;
        }
        t5_0[k] = s0;
        t5_1[k] = s1;
    }

    // ---- Stage IV: out[n0n1][n2n3] = sum_r t5[r][n0n1] * H[r][n2n3] ----
    float4 hreg[8];
    {
        const float4* H4 = (const float4*)Hs;
#pragma unroll
        for (int r = 0; r < 8; r++) hreg[r] = H4[r * 16 + lo];
    }
#pragma unroll
    for (int half = 0; half < 2; half++) {
#pragma unroll 4
        for (int s2 = 0; s2 < 16; s2++) {
            const int seg = half * 16 + s2;
            const int src = (seg * 2 + hi) & 31;
            float4 acc0 = make_float4(0.f, 0.f, 0.f, 0.f);
            float4 acc1 = make_float4(0.f, 0.f, 0.f, 0.f);
#pragma unroll
            for (int r = 0; r < 8; r++) {
                const float s0 = __shfl_sync(FULL, t5_0[2 * r + half], src);
                const float s1 = __shfl_sync(FULL, t5_1[2 * r + half], src);
                acc0.x = fmaf(s0, hreg[r].x, acc0.x);
                acc0.y = fmaf(s0, hreg[r].y, acc0.y);
                acc0.z = fmaf(s0, hreg[r].z, acc0.z);
                acc0.w = fmaf(s0, hreg[r].w, acc0.w);
                acc1.x = fmaf(s1, hreg[r].x, acc1.x);
                acc1.y = fmaf(s1, hreg[r].y, acc1.y);
                acc1.z = fmaf(s1, hreg[r].z, acc1.z);
                acc1.w = fmaf(s1, hreg[r].w, acc1.w);
            }
            *(float4*)(o0 + seg * 128 + l * 4) = acc0;
            *(float4*)(o1 + seg * 128 + l * 4) = acc1;
        }
    }
}

extern "C" void kernel_launch(void* const* d_in, const int* in_sizes, int n_in,
                              void* d_out, int out_size)
{
    const float* X     = (const float*)d_in[0];
    const float* gates = (const float*)d_in[1];
    const float* cf    = (const float*)d_in[2];
    const float* cm    = (const float*)d_in[3];
    const float* cl    = (const float*)d_in[4];
    float* out = (float*)d_out;

    tt_prep<<<8, 256>>>(gates, cf, cm, cl);
    tt_main<<<256, 256>>>(X, out);
}